// round 12
// baseline (speedup 1.0000x reference)
#include <cuda_runtime.h>
#include <cuda_bf16.h>
#include <cstdint>

#define N_PROJ 400000
#define N_SP   40000
#define D_     256
#define H_     8
#define SP_PAD 40064   // 313 * 128
#define XR_TILES 313
#define BUCKET_CAP 64

// -------- scratch (device globals; no runtime alloc) --------
__device__ uint16_t g_xlb[(size_t)N_PROJ * D_];   // xl bf16; row = [half0 256B][half1 256B]
__device__ float g_xagg[(size_t)SP_PAD * D_];
__device__ float g_xr[(size_t)SP_PAD * D_];
__device__ float g_xskip[(size_t)SP_PAD * D_];
__device__ float g_hbuf[(size_t)SP_PAD * D_];
__device__ float g_wr[3][(size_t)D_ * D_];        // tf32(rna)-rounded weights
__device__ int   g_cnt[N_SP];
__device__ int   g_bucket[(size_t)N_SP * BUCKET_CAP];

// ======================= helpers =======================
static __device__ __forceinline__ uint32_t smem_u32(const void* p) {
    uint32_t a;
    asm("{ .reg .u64 t; cvta.to.shared.u64 t, %1; cvt.u32.u64 %0, t; }"
        : "=r"(a) : "l"(p));
    return a;
}
static __device__ __forceinline__ uint32_t f2tf32(float f) {
    uint32_t r;
    asm("cvt.rna.tf32.f32 %0, %1;" : "=r"(r) : "f"(f));
    return r;
}
static __device__ __forceinline__ float roundtf(float f) {
    return __uint_as_float(f2tf32(f));
}
#define CPA16(dst, src) \
    asm volatile("cp.async.cg.shared.global [%0], [%1], 16;" :: "r"(dst), "l"(src))
#define CPA_COMMIT() asm volatile("cp.async.commit_group;" ::: "memory")
#define CPA_WAIT(n)  asm volatile("cp.async.wait_group %0;" :: "n"(n) : "memory")

static __device__ __forceinline__ void mma_tf32(float* c, const uint32_t* a,
                                                const uint32_t* b) {
    asm volatile(
        "mma.sync.aligned.m16n8k8.row.col.f32.tf32.tf32.f32 "
        "{%0,%1,%2,%3}, {%4,%5,%6,%7}, {%8,%9}, {%0,%1,%2,%3};"
        : "+f"(c[0]), "+f"(c[1]), "+f"(c[2]), "+f"(c[3])
        : "r"(a[0]), "r"(a[1]), "r"(a[2]), "r"(a[3]), "r"(b[0]), "r"(b[1]));
}

// byte offset of column cc in a permuted bf16 row: half-contiguous layout
// half w = cc>>7 at bytes [256w, 256w+256); within: (c>>2)*8 + (c&3)*2
static __device__ __forceinline__ int bfoff(int cc) {
    int c = cc & 127;
    return ((cc >> 7) << 8) + (c >> 2) * 8 + (c & 3) * 2;
}

// ======================= round 3 weight matrices to tf32 (one launch) =======================
__global__ void round_w3(const float* __restrict__ w0, const float* __restrict__ w1,
                         const float* __restrict__ w2, float* __restrict__ out) {
    int b = blockIdx.x;
    int i = (b & 255) * 256 + threadIdx.x;
    const float* src = (b < 256) ? w0 : (b < 512) ? w1 : w2;
    out[(size_t)(b >> 8) * D_ * D_ + i] = roundtf(src[i]);
}

// ======================= GEMM tile constants =======================
#define BM 128
#define BN 128
#define BK 32
#define GK 256
#define NKT (GK / BK)
#define AS_STRIDE 36
#define BS_STRIDE 136
#define A_WORDS (BM * AS_STRIDE)
#define B_WORDS (BK * BS_STRIDE)
#define STAGE_WORDS (A_WORDS + B_WORDS)
#define GEMM_SMEM (3 * STAGE_WORDS * 4)   // 107520 B

#define GEMM_PROLOGUE_BODY(Aptr, Wptr)                                          \
    float c[4][4][4];                                                           \
    _Pragma("unroll")                                                           \
    for (int i = 0; i < 4; i++)                                                 \
        _Pragma("unroll")                                                       \
        for (int j = 0; j < 4; j++)                                             \
            { c[i][j][0]=0.f; c[i][j][1]=0.f; c[i][j][2]=0.f; c[i][j][3]=0.f; } \
    uint32_t sbase = smem_u32(sm);                                              \
    auto issue_stage = [&](int kt, int buf) {                                   \
        uint32_t abase = sbase + buf * STAGE_WORDS * 4;                         \
        uint32_t bbase = abase + A_WORDS * 4;                                   \
        int k0 = kt * BK;                                                       \
        _Pragma("unroll")                                                       \
        for (int i = 0; i < 4; i++) {                                           \
            int idx = i * 256 + tid;                                            \
            int r = idx >> 3, cq = idx & 7;                                     \
            CPA16(abase + (r * AS_STRIDE + cq * 4) * 4,                         \
                  Aptr + (size_t)(row0 + r) * GK + k0 + cq * 4);                \
        }                                                                       \
        _Pragma("unroll")                                                       \
        for (int i = 0; i < 4; i++) {                                           \
            int idx = i * 256 + tid;                                            \
            int r = idx >> 5, cq = idx & 31;                                    \
            CPA16(bbase + (r * BS_STRIDE + cq * 4) * 4,                         \
                  Wptr + (size_t)(k0 + r) * GK + col0 + cq * 4);                \
        }                                                                       \
        CPA_COMMIT();                                                           \
    };                                                                          \
    issue_stage(0, 0);                                                          \
    issue_stage(1, 1);                                                          \
    for (int kt = 0; kt < NKT; ++kt) {                                          \
        int buf = kt % 3;                                                       \
        if (kt + 2 < NKT) { issue_stage(kt + 2, (kt + 2) % 3); CPA_WAIT(2); }   \
        else if (kt + 1 < NKT) { CPA_WAIT(1); }                                 \
        else { CPA_WAIT(0); }                                                   \
        __syncthreads();                                                        \
        const float* As = sm + buf * STAGE_WORDS;                               \
        const float* Bs = As + A_WORDS;                                         \
        _Pragma("unroll")                                                       \
        for (int k8 = 0; k8 < BK / 8; k8++) {                                   \
            int kk = k8 * 8;                                                    \
            uint32_t af[4][4], bf[4][2];                                        \
            _Pragma("unroll")                                                   \
            for (int mt = 0; mt < 4; mt++) {                                    \
                int m = wm + mt * 16;                                           \
                af[mt][0] = __float_as_uint(As[(m + g) * AS_STRIDE + kk + t]);  \
                af[mt][1] = __float_as_uint(As[(m + g + 8) * AS_STRIDE + kk + t]); \
                af[mt][2] = __float_as_uint(As[(m + g) * AS_STRIDE + kk + t + 4]); \
                af[mt][3] = __float_as_uint(As[(m + g + 8) * AS_STRIDE + kk + t + 4]); \
            }                                                                   \
            _Pragma("unroll")                                                   \
            for (int nt = 0; nt < 4; nt++) {                                    \
                int n = wn + nt * 8;                                            \
                bf[nt][0] = __float_as_uint(Bs[(kk + t) * BS_STRIDE + n + g]);  \
                bf[nt][1] = __float_as_uint(Bs[(kk + t + 4) * BS_STRIDE + n + g]); \
            }                                                                   \
            _Pragma("unroll")                                                   \
            for (int mt = 0; mt < 4; mt++)                                      \
                _Pragma("unroll")                                               \
                for (int nt = 0; nt < 4; nt++)                                  \
                    mma_tf32(c[mt][nt], af[mt], bf[nt]);                        \
        }                                                                       \
        __syncthreads();                                                        \
    }

// ======================= fused xr + xl GEMM =======================
// blockIdx.y < XR_TILES: xr = xagg@Wr+br (fp32). Else: xl = proj@Wl+bl (bf16 permuted).
__global__ void __launch_bounds__(256, 2)
gemm_xr_xl(const float* __restrict__ Axr, const float* __restrict__ Wxr,
           const float* __restrict__ bxr, float* __restrict__ Cxr,
           const float* __restrict__ Axl, const float* __restrict__ Wxl,
           const float* __restrict__ bxl, uint16_t* __restrict__ Cxl)
{
    extern __shared__ float sm[];
    const int tid = threadIdx.x;
    const int wid = tid >> 5, lane = tid & 31;
    const int g = lane >> 2, t = lane & 3;
    const int wm = (wid >> 2) * 64;
    const int wn = (wid & 3) * 32;
    const bool isXr = blockIdx.y < XR_TILES;
    const int row0 = (isXr ? blockIdx.y : (blockIdx.y - XR_TILES)) * BM;
    const int col0 = blockIdx.x * BN;
    const float* A = isXr ? Axr : Axl;
    const float* W = isXr ? Wxr : Wxl;
    const float* bias = isXr ? bxr : bxl;

    GEMM_PROLOGUE_BODY(A, W)

    if (isXr) {
        #pragma unroll
        for (int mt = 0; mt < 4; mt++) {
            int r0 = row0 + wm + mt * 16 + g;
            int r1 = r0 + 8;
            #pragma unroll
            for (int nt = 0; nt < 4; nt++) {
                int cc = col0 + wn + nt * 8 + 2 * t;
                float b0 = bias[cc], b1 = bias[cc + 1];
                if (r0 < N_SP) {
                    float2 v = { c[mt][nt][0] + b0, c[mt][nt][1] + b1 };
                    *(float2*)(Cxr + (size_t)r0 * D_ + cc) = v;
                }
                if (r1 < N_SP) {
                    float2 v = { c[mt][nt][2] + b0, c[mt][nt][3] + b1 };
                    *(float2*)(Cxr + (size_t)r1 * D_ + cc) = v;
                }
            }
        }
    } else {
        #pragma unroll
        for (int mt = 0; mt < 4; mt++) {
            int r0 = row0 + wm + mt * 16 + g;
            int r1 = r0 + 8;
            char* rp0 = (char*)(Cxl + (size_t)r0 * D_);
            char* rp1 = (char*)(Cxl + (size_t)r1 * D_);
            #pragma unroll
            for (int nt = 0; nt < 4; nt++) {
                int cc = col0 + wn + nt * 8 + 2 * t;
                float b0 = bias[cc], b1 = bias[cc + 1];
                int off = bfoff(cc);
                __nv_bfloat162 h0 = __floats2bfloat162_rn(c[mt][nt][0] + b0,
                                                          c[mt][nt][1] + b1);
                __nv_bfloat162 h1 = __floats2bfloat162_rn(c[mt][nt][2] + b0,
                                                          c[mt][nt][3] + b1);
                *(__nv_bfloat162*)(rp0 + off) = h0;
                *(__nv_bfloat162*)(rp1 + off) = h1;
            }
        }
    }
}

// ======================= plain GEMM (mlp) =======================
__global__ void __launch_bounds__(256, 2)
mma_gemm(const float* __restrict__ Ag, const float* __restrict__ Wg,
         const float* __restrict__ bias, const float* __restrict__ skip,
         float* __restrict__ C, int Mtot)
{
    extern __shared__ float sm[];
    const int tid = threadIdx.x;
    const int wid = tid >> 5, lane = tid & 31;
    const int g = lane >> 2, t = lane & 3;
    const int wm = (wid >> 2) * 64;
    const int wn = (wid & 3) * 32;
    const int row0 = blockIdx.y * BM;
    const int col0 = blockIdx.x * BN;

    GEMM_PROLOGUE_BODY(Ag, Wg)

    #pragma unroll
    for (int mt = 0; mt < 4; mt++) {
        int r0 = row0 + wm + mt * 16 + g;
        int r1 = r0 + 8;
        #pragma unroll
        for (int nt = 0; nt < 4; nt++) {
            int cc = col0 + wn + nt * 8 + 2 * t;
            float b0 = bias[cc], b1 = bias[cc + 1];
            if (r0 < Mtot) {
                float2 v = { c[mt][nt][0] + b0, c[mt][nt][1] + b1 };
                const float2 s2 = *(const float2*)(skip + (size_t)r0 * D_ + cc);
                v.x += s2.x; v.y += s2.y;
                *(float2*)(C + (size_t)r0 * D_ + cc) = v;
            }
            if (r1 < Mtot) {
                float2 v = { c[mt][nt][2] + b0, c[mt][nt][3] + b1 };
                const float2 s2 = *(const float2*)(skip + (size_t)r1 * D_ + cc);
                v.x += s2.x; v.y += s2.y;
                *(float2*)(C + (size_t)r1 * D_ + cc) = v;
            }
        }
    }
}

// ======================= warp reduce helper =======================
static __device__ __forceinline__ void wreduce2(float& s, float& q) {
    #pragma unroll
    for (int o = 16; o; o >>= 1) {
        s += __shfl_xor_sync(0xffffffffu, s, o);
        q += __shfl_xor_sync(0xffffffffu, q, o);
    }
}
#define SUM4(v) ((v).x + (v).y + (v).z + (v).w)
#define SUMSQ4(v) ((v).x*(v).x + (v).y*(v).y + (v).z*(v).z + (v).w*(v).w)

// ======================= LN1 + ReLU (tf32 out) + zero cnt — warp/row =======================
__global__ void __launch_bounds__(256)
ln_relu_zero_kernel(const float* __restrict__ x,
                    const float* __restrict__ g,
                    const float* __restrict__ b,
                    float* __restrict__ out,
                    int* __restrict__ cnt) {
    int row = blockIdx.x * 8 + (threadIdx.x >> 5);
    int lane = threadIdx.x & 31;
    if (lane == 0) cnt[row] = 0;

    const float4* xp = (const float4*)(x + (size_t)row * D_);
    float4 v0 = xp[lane], v1 = xp[lane + 32];
    float s = SUM4(v0) + SUM4(v1);
    float q = SUMSQ4(v0) + SUMSQ4(v1);
    wreduce2(s, q);
    float mean = s * (1.f / 256.f);
    float var  = q * (1.f / 256.f) - mean * mean;
    float rstd = rsqrtf(var + 1e-5f);

    float4 g0 = ((const float4*)g)[lane], g1 = ((const float4*)g)[lane + 32];
    float4 b0 = ((const float4*)b)[lane], b1 = ((const float4*)b)[lane + 32];
    float4 y0, y1;
    y0.x = roundtf(fmaxf((v0.x - mean) * rstd * g0.x + b0.x, 0.f));
    y0.y = roundtf(fmaxf((v0.y - mean) * rstd * g0.y + b0.y, 0.f));
    y0.z = roundtf(fmaxf((v0.z - mean) * rstd * g0.z + b0.z, 0.f));
    y0.w = roundtf(fmaxf((v0.w - mean) * rstd * g0.w + b0.w, 0.f));
    y1.x = roundtf(fmaxf((v1.x - mean) * rstd * g1.x + b1.x, 0.f));
    y1.y = roundtf(fmaxf((v1.y - mean) * rstd * g1.y + b1.y, 0.f));
    y1.z = roundtf(fmaxf((v1.z - mean) * rstd * g1.z + b1.z, 0.f));
    y1.w = roundtf(fmaxf((v1.w - mean) * rstd * g1.w + b1.w, 0.f));
    float4* op = (float4*)(out + (size_t)row * D_);
    op[lane] = y0; op[lane + 32] = y1;
}

// ======================= bucket fill =======================
__global__ void bucket_fill(const int* __restrict__ etgt,
                            int* __restrict__ cnt, int* __restrict__ bucket) {
    int e = blockIdx.x * 256 + threadIdx.x;
    if (e >= N_PROJ) return;
    int tgt = etgt[e];
    int slot = atomicAdd(cnt + tgt, 1);
    if (slot < BUCKET_CAP) bucket[(size_t)tgt * BUCKET_CAP + slot] = e;
}

// ======================= aggregate + finalize (TWO warps per target) =======================
// warp-half w handles heads 4w..4w+3 = dims 128w..128w+127.
__global__ void __launch_bounds__(256)
agg_finalize(const int* __restrict__ cnt, const int* __restrict__ bucket,
             const int* __restrict__ esrc, const float* __restrict__ att,
             const uint16_t* __restrict__ xlb, const float* __restrict__ xr,
             const float* __restrict__ prev, const float* __restrict__ gat_bias,
             const float* __restrict__ g2, const float* __restrict__ b2,
             float* __restrict__ xskip, float* __restrict__ hbuf)
{
    __shared__ float ssum[4][2], sqsum[4][2];
    int warp = threadIdx.x >> 5;
    int tp = warp >> 1;          // target slot in CTA: 0..3
    int w = warp & 1;            // half
    int tgt = blockIdx.x * 4 + tp;
    int lane = threadIdx.x & 31;
    int n = min(cnt[tgt], BUCKET_CAP);
    int dbase = 128 * w + 4 * lane;   // this lane's 4 dims

    float4 r0 = *(const float4*)(xr + (size_t)tgt * 256 + dbase);
    int head = 4 * w + (lane >> 3);
    const float4 wv = *(const float4*)(att + head * 32 + ((lane & 7) << 2));

    const int* bp = bucket + (size_t)tgt * BUCKET_CAP;
    int sA = 0, sB = 0;
    if (lane < n)      sA = esrc[bp[lane]];
    if (lane + 32 < n) sB = esrc[bp[lane + 32]];

    auto loadrow = [&](int i) {
        int s = (i < 32) ? __shfl_sync(0xffffffffu, sA, i)
                         : __shfl_sync(0xffffffffu, sB, i - 32);
        return *(const uint2*)((const char*)(xlb + (size_t)s * 256) + w * 256 + lane * 8);
    };

    float4 acc = {0.f, 0.f, 0.f, 0.f};
    float den = 0.f;

    uint2 q0 = {}, q1 = {};
    if (n > 0) q0 = loadrow(0);
    if (n > 1) q1 = loadrow(1);

    for (int i = 0; i < n; i++) {
        uint2 qn = {};
        if (i + 2 < n) qn = loadrow(i + 2);

        float2 f0 = __bfloat1622float2(*(const __nv_bfloat162*)&q0.x);
        float2 f1 = __bfloat1622float2(*(const __nv_bfloat162*)&q0.y);
        float4 a = { f0.x, f0.y, f1.x, f1.y };

        #define LREL(x) (fmaxf((x), 0.f) + 0.2f * fminf((x), 0.f))
        float p = LREL(a.x + r0.x) * wv.x + LREL(a.y + r0.y) * wv.y +
                  LREL(a.z + r0.z) * wv.z + LREL(a.w + r0.w) * wv.w;
        #undef LREL
        #pragma unroll
        for (int o = 4; o; o >>= 1)
            p += __shfl_xor_sync(0xffffffffu, p, o);
        float ex = expf(p);
        acc.x += ex * a.x; acc.y += ex * a.y;
        acc.z += ex * a.z; acc.w += ex * a.w;
        den += ex;

        q0 = q1; q1 = qn;
    }

    // ---- finalize for this half-row ----
    float inv = 1.f / (den + 1e-16f);
    float4 p0 = *(const float4*)(prev + (size_t)tgt * D_ + dbase);
    float4 gb = *(const float4*)(gat_bias + dbase);
    float4 x0;
    x0.x = p0.x + acc.x * inv + gb.x;
    x0.y = p0.y + acc.y * inv + gb.y;
    x0.z = p0.z + acc.z * inv + gb.z;
    x0.w = p0.w + acc.w * inv + gb.w;
    *(float4*)(xskip + (size_t)tgt * D_ + dbase) = x0;

    float s = SUM4(x0);
    float q = SUMSQ4(x0);
    wreduce2(s, q);
    if (lane == 0) { ssum[tp][w] = s; sqsum[tp][w] = q; }
    __syncthreads();
    float tot  = ssum[tp][0] + ssum[tp][1];
    float totq = sqsum[tp][0] + sqsum[tp][1];
    float mean = tot * (1.f / 256.f);
    float var  = totq * (1.f / 256.f) - mean * mean;
    float rstd = rsqrtf(var + 1e-5f);

    float4 g0 = *(const float4*)(g2 + dbase);
    float4 bb = *(const float4*)(b2 + dbase);
    float4 y;
    y.x = roundtf(fmaxf((x0.x - mean) * rstd * g0.x + bb.x, 0.f));
    y.y = roundtf(fmaxf((x0.y - mean) * rstd * g0.y + bb.y, 0.f));
    y.z = roundtf(fmaxf((x0.z - mean) * rstd * g0.z + bb.z, 0.f));
    y.w = roundtf(fmaxf((x0.w - mean) * rstd * g0.w + bb.w, 0.f));
    *(float4*)(hbuf + (size_t)tgt * D_ + dbase) = y;
}

// ======================= launch =======================
extern "C" void kernel_launch(void* const* d_in, const int* in_sizes, int n_in,
                              void* d_out, int out_size) {
    const float* proj     = (const float*)d_in[0];
    const float* prev     = (const float*)d_in[1];
    const float* Wl       = (const float*)d_in[2];
    const float* bl       = (const float*)d_in[3];
    const float* Wr       = (const float*)d_in[4];
    const float* br       = (const float*)d_in[5];
    const float* att      = (const float*)d_in[6];
    const float* gat_bias = (const float*)d_in[7];
    const float* ln1_g    = (const float*)d_in[8];
    const float* ln1_b    = (const float*)d_in[9];
    const float* ln2_g    = (const float*)d_in[10];
    const float* ln2_b    = (const float*)d_in[11];
    const float* mlp_W    = (const float*)d_in[12];
    const float* mlp_b    = (const float*)d_in[13];
    const int*   esrc     = (const int*)d_in[14];
    const int*   etgt     = (const int*)d_in[15];
    float* out = (float*)d_out;

    float *p_xagg, *p_xr, *p_xskip, *p_hbuf, *p_wr;
    uint16_t* p_xlb;
    int *p_cnt, *p_bucket;
    cudaGetSymbolAddress((void**)&p_xlb, g_xlb);
    cudaGetSymbolAddress((void**)&p_xagg, g_xagg);
    cudaGetSymbolAddress((void**)&p_xr, g_xr);
    cudaGetSymbolAddress((void**)&p_xskip, g_xskip);
    cudaGetSymbolAddress((void**)&p_hbuf, g_hbuf);
    cudaGetSymbolAddress((void**)&p_wr, g_wr);
    cudaGetSymbolAddress((void**)&p_cnt, g_cnt);
    cudaGetSymbolAddress((void**)&p_bucket, g_bucket);
    float* wlR  = p_wr;
    float* wrR  = p_wr + (size_t)D_ * D_;
    float* mlpR = p_wr + 2 * (size_t)D_ * D_;

    cudaFuncSetAttribute(mma_gemm, cudaFuncAttributeMaxDynamicSharedMemorySize, GEMM_SMEM);
    cudaFuncSetAttribute(gemm_xr_xl, cudaFuncAttributeMaxDynamicSharedMemorySize, GEMM_SMEM);

    // 0) pre-round weights to tf32 (rna), single launch
    round_w3<<<768, 256>>>(Wl, Wr, mlp_W, p_wr);

    // 1) x_agg = relu(LN1(prev)) (tf32) + zero bucket counters
    ln_relu_zero_kernel<<<N_SP / 8, 256>>>(prev, ln1_g, ln1_b, p_xagg, p_cnt);

    // 2) bucket edges by target
    bucket_fill<<<(N_PROJ + 255) / 256, 256>>>(etgt, p_cnt, p_bucket);

    // 3) fused xr + xl GEMM (xr tail overlaps xl waves)
    {
        dim3 grid(D_ / BN, XR_TILES + N_PROJ / BM);
        gemm_xr_xl<<<grid, 256, GEMM_SMEM>>>(p_xagg, wrR, br, p_xr,
                                             proj, wlR, bl, p_xlb);
    }

    // 4) aggregate per-target (2 warps/tgt) + finalize, fused
    agg_finalize<<<N_SP / 4, 256>>>(p_cnt, p_bucket, esrc, att, p_xlb, p_xr,
                                    prev, gat_bias, ln2_g, ln2_b, p_xskip, p_hbuf);

    // 5) out = xskip + hbuf @ mlp_W + mlp_b
    {
        dim3 grid(D_ / BN, SP_PAD / BM);
        mma_gemm<<<grid, 256, GEMM_SMEM>>>(p_hbuf, mlpR, mlp_b, p_xskip, out, N_SP);
    }
}

// round 13
// speedup vs baseline: 1.0453x; 1.0453x over previous
#include <cuda_runtime.h>
#include <cuda_bf16.h>
#include <cstdint>

#define N_PROJ 400000
#define N_SP   40000
#define D_     256
#define H_     8
#define SP_PAD 40064   // 313 * 128
#define BUCKET_CAP 64

// -------- scratch (device globals; no runtime alloc) --------
__device__ uint16_t g_xlb[(size_t)N_PROJ * D_];   // xl in bf16, permuted chunks
__device__ float g_xagg[(size_t)SP_PAD * D_];
__device__ float g_xr[(size_t)SP_PAD * D_];
__device__ float g_xskip[(size_t)SP_PAD * D_];
__device__ float g_hbuf[(size_t)SP_PAD * D_];
__device__ float g_wr[3][(size_t)D_ * D_];        // tf32(rna)-rounded weights
__device__ int   g_cnt[N_SP];
__device__ int   g_bucket[(size_t)N_SP * BUCKET_CAP];

// ======================= helpers =======================
static __device__ __forceinline__ uint32_t smem_u32(const void* p) {
    uint32_t a;
    asm("{ .reg .u64 t; cvta.to.shared.u64 t, %1; cvt.u32.u64 %0, t; }"
        : "=r"(a) : "l"(p));
    return a;
}
static __device__ __forceinline__ uint32_t f2tf32(float f) {
    uint32_t r;
    asm("cvt.rna.tf32.f32 %0, %1;" : "=r"(r) : "f"(f));
    return r;
}
static __device__ __forceinline__ float roundtf(float f) {
    return __uint_as_float(f2tf32(f));
}
#define CPA16(dst, src) \
    asm volatile("cp.async.cg.shared.global [%0], [%1], 16;" :: "r"(dst), "l"(src))
#define CPA_COMMIT() asm volatile("cp.async.commit_group;" ::: "memory")
#define CPA_WAIT(n)  asm volatile("cp.async.wait_group %0;" :: "n"(n) : "memory")

static __device__ __forceinline__ void mma_tf32(float* c, const uint32_t* a,
                                                const uint32_t* b) {
    asm volatile(
        "mma.sync.aligned.m16n8k8.row.col.f32.tf32.tf32.f32 "
        "{%0,%1,%2,%3}, {%4,%5,%6,%7}, {%8,%9}, {%0,%1,%2,%3};"
        : "+f"(c[0]), "+f"(c[1]), "+f"(c[2]), "+f"(c[3])
        : "r"(a[0]), "r"(a[1]), "r"(a[2]), "r"(a[3]), "r"(b[0]), "r"(b[1]));
}

// byte offset of column cc within a permuted bf16 row (lane chunk layout):
// lane l owns bytes [16l,16l+16): cols {4l..4l+3} then {128+4l..128+4l+3}
static __device__ __forceinline__ int bfoff(int cc) {
    int c = cc & 127;
    int hi = (cc >> 7) & 1;
    return (c >> 2) * 16 + hi * 8 + (c & 3) * 2;
}

// ======================= round 3 weight matrices to tf32 (one launch) =======================
__global__ void round_w3(const float* __restrict__ w0, const float* __restrict__ w1,
                         const float* __restrict__ w2, float* __restrict__ out) {
    int b = blockIdx.x;
    int i = (b & 255) * 256 + threadIdx.x;
    const float* src = (b < 256) ? w0 : (b < 512) ? w1 : w2;
    out[(size_t)(b >> 8) * D_ * D_ + i] = roundtf(src[i]);
}

// ======================= tf32 mma.sync GEMM (cvt-free, 3-stage) =======================
// If Cb != nullptr: write bf16 permuted rows to Cb (xl path). Else fp32 to C.
#define BM 128
#define BN 128
#define BK 32
#define GK 256
#define NKT (GK / BK)
#define AS_STRIDE 36
#define BS_STRIDE 136
#define A_WORDS (BM * AS_STRIDE)
#define B_WORDS (BK * BS_STRIDE)
#define STAGE_WORDS (A_WORDS + B_WORDS)
#define GEMM_SMEM (3 * STAGE_WORDS * 4)   // 107520 B

__global__ void __launch_bounds__(256, 2)
mma_gemm(const float* __restrict__ A, const float* __restrict__ W,
         const float* __restrict__ bias, const float* __restrict__ skip,
         float* __restrict__ C, uint16_t* __restrict__ Cb, int Mtot)
{
    extern __shared__ float sm[];
    const int tid = threadIdx.x;
    const int wid = tid >> 5, lane = tid & 31;
    const int g = lane >> 2, t = lane & 3;
    const int wm = (wid >> 2) * 64;
    const int wn = (wid & 3) * 32;
    const int row0 = blockIdx.y * BM;
    const int col0 = blockIdx.x * BN;

    float c[4][4][4];
    #pragma unroll
    for (int i = 0; i < 4; i++)
        #pragma unroll
        for (int j = 0; j < 4; j++)
            { c[i][j][0] = 0.f; c[i][j][1] = 0.f; c[i][j][2] = 0.f; c[i][j][3] = 0.f; }

    uint32_t sbase = smem_u32(sm);

    auto issue_stage = [&](int kt, int buf) {
        uint32_t abase = sbase + buf * STAGE_WORDS * 4;
        uint32_t bbase = abase + A_WORDS * 4;
        int k0 = kt * BK;
        #pragma unroll
        for (int i = 0; i < 4; i++) {
            int idx = i * 256 + tid;
            int r = idx >> 3, cq = idx & 7;
            CPA16(abase + (r * AS_STRIDE + cq * 4) * 4,
                  A + (size_t)(row0 + r) * GK + k0 + cq * 4);
        }
        #pragma unroll
        for (int i = 0; i < 4; i++) {
            int idx = i * 256 + tid;
            int r = idx >> 5, cq = idx & 31;
            CPA16(bbase + (r * BS_STRIDE + cq * 4) * 4,
                  W + (size_t)(k0 + r) * GK + col0 + cq * 4);
        }
        CPA_COMMIT();
    };

    issue_stage(0, 0);
    issue_stage(1, 1);

    for (int kt = 0; kt < NKT; ++kt) {
        int buf = kt % 3;
        if (kt + 2 < NKT) { issue_stage(kt + 2, (kt + 2) % 3); CPA_WAIT(2); }
        else if (kt + 1 < NKT) { CPA_WAIT(1); }
        else { CPA_WAIT(0); }
        __syncthreads();

        const float* As = sm + buf * STAGE_WORDS;
        const float* Bs = As + A_WORDS;

        #pragma unroll
        for (int k8 = 0; k8 < BK / 8; k8++) {
            int kk = k8 * 8;
            uint32_t af[4][4], bf[4][2];
            #pragma unroll
            for (int mt = 0; mt < 4; mt++) {
                int m = wm + mt * 16;
                af[mt][0] = __float_as_uint(As[(m + g) * AS_STRIDE + kk + t]);
                af[mt][1] = __float_as_uint(As[(m + g + 8) * AS_STRIDE + kk + t]);
                af[mt][2] = __float_as_uint(As[(m + g) * AS_STRIDE + kk + t + 4]);
                af[mt][3] = __float_as_uint(As[(m + g + 8) * AS_STRIDE + kk + t + 4]);
            }
            #pragma unroll
            for (int nt = 0; nt < 4; nt++) {
                int n = wn + nt * 8;
                bf[nt][0] = __float_as_uint(Bs[(kk + t) * BS_STRIDE + n + g]);
                bf[nt][1] = __float_as_uint(Bs[(kk + t + 4) * BS_STRIDE + n + g]);
            }
            #pragma unroll
            for (int mt = 0; mt < 4; mt++)
                #pragma unroll
                for (int nt = 0; nt < 4; nt++)
                    mma_tf32(c[mt][nt], af[mt], bf[nt]);
        }
        __syncthreads();
    }

    if (Cb) {
        // bf16 permuted epilogue (xl path; no skip)
        #pragma unroll
        for (int mt = 0; mt < 4; mt++) {
            int r0 = row0 + wm + mt * 16 + g;
            int r1 = r0 + 8;
            char* rp0 = (char*)(Cb + (size_t)r0 * D_);
            char* rp1 = (char*)(Cb + (size_t)r1 * D_);
            #pragma unroll
            for (int nt = 0; nt < 4; nt++) {
                int cc = col0 + wn + nt * 8 + 2 * t;
                float b0 = bias[cc], b1 = bias[cc + 1];
                int off = bfoff(cc);
                __nv_bfloat162 h0 = __floats2bfloat162_rn(c[mt][nt][0] + b0,
                                                          c[mt][nt][1] + b1);
                __nv_bfloat162 h1 = __floats2bfloat162_rn(c[mt][nt][2] + b0,
                                                          c[mt][nt][3] + b1);
                *(__nv_bfloat162*)(rp0 + off) = h0;
                *(__nv_bfloat162*)(rp1 + off) = h1;
            }
        }
    } else {
        #pragma unroll
        for (int mt = 0; mt < 4; mt++) {
            int r0 = row0 + wm + mt * 16 + g;
            int r1 = r0 + 8;
            #pragma unroll
            for (int nt = 0; nt < 4; nt++) {
                int cc = col0 + wn + nt * 8 + 2 * t;
                float b0 = bias[cc], b1 = bias[cc + 1];
                if (r0 < Mtot) {
                    float2 v = { c[mt][nt][0] + b0, c[mt][nt][1] + b1 };
                    if (skip) {
                        const float2 s2 = *(const float2*)(skip + (size_t)r0 * D_ + cc);
                        v.x += s2.x; v.y += s2.y;
                    }
                    *(float2*)(C + (size_t)r0 * D_ + cc) = v;
                }
                if (r1 < Mtot) {
                    float2 v = { c[mt][nt][2] + b0, c[mt][nt][3] + b1 };
                    if (skip) {
                        const float2 s2 = *(const float2*)(skip + (size_t)r1 * D_ + cc);
                        v.x += s2.x; v.y += s2.y;
                    }
                    *(float2*)(C + (size_t)r1 * D_ + cc) = v;
                }
            }
        }
    }
}

// ======================= warp reduce helper =======================
static __device__ __forceinline__ void wreduce2(float& s, float& q) {
    #pragma unroll
    for (int o = 16; o; o >>= 1) {
        s += __shfl_xor_sync(0xffffffffu, s, o);
        q += __shfl_xor_sync(0xffffffffu, q, o);
    }
}
#define SUM4(v) ((v).x + (v).y + (v).z + (v).w)
#define SUMSQ4(v) ((v).x*(v).x + (v).y*(v).y + (v).z*(v).z + (v).w*(v).w)

// ======================= LN1 + ReLU (tf32 out) + zero cnt — warp/row =======================
__global__ void __launch_bounds__(256)
ln_relu_zero_kernel(const float* __restrict__ x,
                    const float* __restrict__ g,
                    const float* __restrict__ b,
                    float* __restrict__ out,
                    int* __restrict__ cnt) {
    int row = blockIdx.x * 8 + (threadIdx.x >> 5);
    int lane = threadIdx.x & 31;
    if (lane == 0) cnt[row] = 0;

    const float4* xp = (const float4*)(x + (size_t)row * D_);
    float4 v0 = xp[lane], v1 = xp[lane + 32];
    float s = SUM4(v0) + SUM4(v1);
    float q = SUMSQ4(v0) + SUMSQ4(v1);
    wreduce2(s, q);
    float mean = s * (1.f / 256.f);
    float var  = q * (1.f / 256.f) - mean * mean;
    float rstd = rsqrtf(var + 1e-5f);

    float4 g0 = ((const float4*)g)[lane], g1 = ((const float4*)g)[lane + 32];
    float4 b0 = ((const float4*)b)[lane], b1 = ((const float4*)b)[lane + 32];
    float4 y0, y1;
    y0.x = roundtf(fmaxf((v0.x - mean) * rstd * g0.x + b0.x, 0.f));
    y0.y = roundtf(fmaxf((v0.y - mean) * rstd * g0.y + b0.y, 0.f));
    y0.z = roundtf(fmaxf((v0.z - mean) * rstd * g0.z + b0.z, 0.f));
    y0.w = roundtf(fmaxf((v0.w - mean) * rstd * g0.w + b0.w, 0.f));
    y1.x = roundtf(fmaxf((v1.x - mean) * rstd * g1.x + b1.x, 0.f));
    y1.y = roundtf(fmaxf((v1.y - mean) * rstd * g1.y + b1.y, 0.f));
    y1.z = roundtf(fmaxf((v1.z - mean) * rstd * g1.z + b1.z, 0.f));
    y1.w = roundtf(fmaxf((v1.w - mean) * rstd * g1.w + b1.w, 0.f));
    float4* op = (float4*)(out + (size_t)row * D_);
    op[lane] = y0; op[lane + 32] = y1;
}

// ======================= bucket fill: edges -> per-target slots =======================
__global__ void bucket_fill(const int* __restrict__ etgt,
                            int* __restrict__ cnt, int* __restrict__ bucket) {
    int e = blockIdx.x * 256 + threadIdx.x;
    if (e >= N_PROJ) return;
    int tgt = etgt[e];
    int slot = atomicAdd(cnt + tgt, 1);
    if (slot < BUCKET_CAP) bucket[(size_t)tgt * BUCKET_CAP + slot] = e;
}

// ======================= aggregate + finalize (one warp per target, depth-4 prefetch) =======================
__global__ void __launch_bounds__(256)
agg_finalize(const int* __restrict__ cnt, const int* __restrict__ bucket,
             const int* __restrict__ esrc, const float* __restrict__ att,
             const uint16_t* __restrict__ xlb, const float* __restrict__ xr,
             const float* __restrict__ prev, const float* __restrict__ gat_bias,
             const float* __restrict__ g2, const float* __restrict__ b2,
             float* __restrict__ xskip, float* __restrict__ hbuf)
{
    int tgt = blockIdx.x * 8 + (threadIdx.x >> 5);
    int lane = threadIdx.x & 31;
    int n = min(cnt[tgt], BUCKET_CAP);

    const float4* xrp = (const float4*)(xr + (size_t)tgt * 256);
    float4 r0 = xrp[lane], r1 = xrp[lane + 32];
    int h1 = lane >> 3;
    const float4 w0 = *(const float4*)(att + h1 * 32 + ((lane & 7) << 2));
    const float4 w1 = *(const float4*)(att + (h1 + 4) * 32 + ((lane & 7) << 2));

    const int* bp = bucket + (size_t)tgt * BUCKET_CAP;
    int sA = 0, sB = 0;
    if (lane < n)      sA = esrc[bp[lane]];
    if (lane + 32 < n) sB = esrc[bp[lane + 32]];

    auto loadrow = [&](int i) {
        int s = (i < 32) ? __shfl_sync(0xffffffffu, sA, i)
                         : __shfl_sync(0xffffffffu, sB, i - 32);
        return ((const uint4*)(xlb + (size_t)s * 256))[lane];
    };

    float4 acc0 = {0.f,0.f,0.f,0.f}, acc1 = {0.f,0.f,0.f,0.f};
    float den1 = 0.f, den2 = 0.f;

    // depth-4 prefetch ring
    uint4 q0 = {}, q1 = {}, q2 = {}, q3 = {};
    if (n > 0) q0 = loadrow(0);
    if (n > 1) q1 = loadrow(1);
    if (n > 2) q2 = loadrow(2);
    if (n > 3) q3 = loadrow(3);

    for (int i = 0; i < n; i++) {
        uint4 qn = {};
        if (i + 4 < n) qn = loadrow(i + 4);

        // unpack bf16 chunk: 4 bf16x2 -> a0 (cols 4l..), a1 (cols 128+4l..)
        float2 f0 = __bfloat1622float2(*(const __nv_bfloat162*)&q0.x);
        float2 f1 = __bfloat1622float2(*(const __nv_bfloat162*)&q0.y);
        float2 f2 = __bfloat1622float2(*(const __nv_bfloat162*)&q0.z);
        float2 f3 = __bfloat1622float2(*(const __nv_bfloat162*)&q0.w);
        float4 a0 = { f0.x, f0.y, f1.x, f1.y };
        float4 a1 = { f2.x, f2.y, f3.x, f3.y };

        #define LREL(x) (fmaxf((x), 0.f) + 0.2f * fminf((x), 0.f))
        float p1 = LREL(a0.x + r0.x) * w0.x + LREL(a0.y + r0.y) * w0.y +
                   LREL(a0.z + r0.z) * w0.z + LREL(a0.w + r0.w) * w0.w;
        float p2 = LREL(a1.x + r1.x) * w1.x + LREL(a1.y + r1.y) * w1.y +
                   LREL(a1.z + r1.z) * w1.z + LREL(a1.w + r1.w) * w1.w;
        #undef LREL
        #pragma unroll
        for (int o = 4; o; o >>= 1) {
            p1 += __shfl_xor_sync(0xffffffffu, p1, o);
            p2 += __shfl_xor_sync(0xffffffffu, p2, o);
        }
        float ex1 = expf(p1);
        float ex2 = expf(p2);
        acc0.x += ex1 * a0.x; acc0.y += ex1 * a0.y;
        acc0.z += ex1 * a0.z; acc0.w += ex1 * a0.w;
        acc1.x += ex2 * a1.x; acc1.y += ex2 * a1.y;
        acc1.z += ex2 * a1.z; acc1.w += ex2 * a1.w;
        den1 += ex1; den2 += ex2;

        q0 = q1; q1 = q2; q2 = q3; q3 = qn;
    }

    // ---- finalize: x = prev + acc/den + gat_bias; LN2 + relu ----
    float inv1 = 1.f / (den1 + 1e-16f);
    float inv2 = 1.f / (den2 + 1e-16f);
    const float4* pp = (const float4*)(prev + (size_t)tgt * D_);
    float4 p0 = pp[lane], p1v = pp[lane + 32];
    float4 gb0 = ((const float4*)gat_bias)[lane];
    float4 gb1 = ((const float4*)gat_bias)[lane + 32];

    float4 x0, x1;
    x0.x = p0.x + acc0.x * inv1 + gb0.x;
    x0.y = p0.y + acc0.y * inv1 + gb0.y;
    x0.z = p0.z + acc0.z * inv1 + gb0.z;
    x0.w = p0.w + acc0.w * inv1 + gb0.w;
    x1.x = p1v.x + acc1.x * inv2 + gb1.x;
    x1.y = p1v.y + acc1.y * inv2 + gb1.y;
    x1.z = p1v.z + acc1.z * inv2 + gb1.z;
    x1.w = p1v.w + acc1.w * inv2 + gb1.w;

    float4* sk = (float4*)(xskip + (size_t)tgt * D_);
    sk[lane] = x0; sk[lane + 32] = x1;

    float s = SUM4(x0) + SUM4(x1);
    float q = SUMSQ4(x0) + SUMSQ4(x1);
    wreduce2(s, q);
    float mean = s * (1.f / 256.f);
    float var  = q * (1.f / 256.f) - mean * mean;
    float rstd = rsqrtf(var + 1e-5f);

    float4 g0 = ((const float4*)g2)[lane], g1 = ((const float4*)g2)[lane + 32];
    float4 bb0 = ((const float4*)b2)[lane], bb1 = ((const float4*)b2)[lane + 32];
    float4 y0, y1;
    y0.x = roundtf(fmaxf((x0.x - mean) * rstd * g0.x + bb0.x, 0.f));
    y0.y = roundtf(fmaxf((x0.y - mean) * rstd * g0.y + bb0.y, 0.f));
    y0.z = roundtf(fmaxf((x0.z - mean) * rstd * g0.z + bb0.z, 0.f));
    y0.w = roundtf(fmaxf((x0.w - mean) * rstd * g0.w + bb0.w, 0.f));
    y1.x = roundtf(fmaxf((x1.x - mean) * rstd * g1.x + bb1.x, 0.f));
    y1.y = roundtf(fmaxf((x1.y - mean) * rstd * g1.y + bb1.y, 0.f));
    y1.z = roundtf(fmaxf((x1.z - mean) * rstd * g1.z + bb1.z, 0.f));
    y1.w = roundtf(fmaxf((x1.w - mean) * rstd * g1.w + bb1.w, 0.f));
    float4* hp = (float4*)(hbuf + (size_t)tgt * D_);
    hp[lane] = y0; hp[lane + 32] = y1;
}

// ======================= launch =======================
extern "C" void kernel_launch(void* const* d_in, const int* in_sizes, int n_in,
                              void* d_out, int out_size) {
    const float* proj     = (const float*)d_in[0];
    const float* prev     = (const float*)d_in[1];
    const float* Wl       = (const float*)d_in[2];
    const float* bl       = (const float*)d_in[3];
    const float* Wr       = (const float*)d_in[4];
    const float* br       = (const float*)d_in[5];
    const float* att      = (const float*)d_in[6];
    const float* gat_bias = (const float*)d_in[7];
    const float* ln1_g    = (const float*)d_in[8];
    const float* ln1_b    = (const float*)d_in[9];
    const float* ln2_g    = (const float*)d_in[10];
    const float* ln2_b    = (const float*)d_in[11];
    const float* mlp_W    = (const float*)d_in[12];
    const float* mlp_b    = (const float*)d_in[13];
    const int*   esrc     = (const int*)d_in[14];
    const int*   etgt     = (const int*)d_in[15];
    float* out = (float*)d_out;

    float *p_xagg, *p_xr, *p_xskip, *p_hbuf, *p_wr;
    uint16_t* p_xlb;
    int *p_cnt, *p_bucket;
    cudaGetSymbolAddress((void**)&p_xlb, g_xlb);
    cudaGetSymbolAddress((void**)&p_xagg, g_xagg);
    cudaGetSymbolAddress((void**)&p_xr, g_xr);
    cudaGetSymbolAddress((void**)&p_xskip, g_xskip);
    cudaGetSymbolAddress((void**)&p_hbuf, g_hbuf);
    cudaGetSymbolAddress((void**)&p_wr, g_wr);
    cudaGetSymbolAddress((void**)&p_cnt, g_cnt);
    cudaGetSymbolAddress((void**)&p_bucket, g_bucket);
    float* wlR  = p_wr;
    float* wrR  = p_wr + (size_t)D_ * D_;
    float* mlpR = p_wr + 2 * (size_t)D_ * D_;

    cudaFuncSetAttribute(mma_gemm, cudaFuncAttributeMaxDynamicSharedMemorySize, GEMM_SMEM);

    // 0) pre-round weights to tf32 (rna), single launch
    round_w3<<<768, 256>>>(Wl, Wr, mlp_W, p_wr);

    // 1) x_agg = relu(LN1(prev)) (tf32) + zero bucket counters
    ln_relu_zero_kernel<<<N_SP / 8, 256>>>(prev, ln1_g, ln1_b, p_xagg, p_cnt);

    // 2) bucket edges by target
    bucket_fill<<<(N_PROJ + 255) / 256, 256>>>(etgt, p_cnt, p_bucket);

    // 3) xr = x_agg @ Wr + br
    {
        dim3 grid(D_ / BN, SP_PAD / BM);
        mma_gemm<<<grid, 256, GEMM_SMEM>>>(p_xagg, wrR, br, nullptr, p_xr, nullptr, N_SP);
    }

    // 4) xl = proj @ Wl + bl  -> bf16 permuted
    {
        dim3 grid(D_ / BN, N_PROJ / BM);
        mma_gemm<<<grid, 256, GEMM_SMEM>>>(proj, wlR, bl, nullptr, nullptr, p_xlb, N_PROJ);
    }

    // 5) aggregate per-target + finalize (residual + LN2 + relu), fused
    agg_finalize<<<N_SP / 8, 256>>>(p_cnt, p_bucket, esrc, att, p_xlb, p_xr,
                                    prev, gat_bias, ln2_g, ln2_b, p_xskip, p_hbuf);

    // 6) out = xskip + hbuf @ mlp_W + mlp_b
    {
        dim3 grid(D_ / BN, SP_PAD / BM);
        mma_gemm<<<grid, 256, GEMM_SMEM>>>(p_hbuf, mlpR, mlp_b, p_xskip, out, nullptr, N_SP);
    }
}

// round 14
// speedup vs baseline: 1.0809x; 1.0340x over previous
#include <cuda_runtime.h>
#include <cuda_bf16.h>
#include <cstdint>

#define N_PROJ 400000
#define N_SP   40000
#define D_     256
#define H_     8
#define SP_PAD 40064   // 313 * 128
#define BUCKET_CAP 64

// -------- scratch (device globals; no runtime alloc) --------
__device__ uint16_t g_xlb[(size_t)N_PROJ * D_];   // xl in bf16, permuted chunks
__device__ float g_xagg[(size_t)SP_PAD * D_];
__device__ float g_xr[(size_t)SP_PAD * D_];
__device__ float g_xskip[(size_t)SP_PAD * D_];
__device__ float g_hbuf[(size_t)SP_PAD * D_];
__device__ float g_wr[3][(size_t)D_ * D_];        // tf32(rna)-rounded weights
__device__ int   g_cnt[N_SP];
__device__ int   g_bucket[(size_t)N_SP * BUCKET_CAP];

// ======================= helpers =======================
static __device__ __forceinline__ uint32_t smem_u32(const void* p) {
    uint32_t a;
    asm("{ .reg .u64 t; cvta.to.shared.u64 t, %1; cvt.u32.u64 %0, t; }"
        : "=r"(a) : "l"(p));
    return a;
}
static __device__ __forceinline__ uint32_t f2tf32(float f) {
    uint32_t r;
    asm("cvt.rna.tf32.f32 %0, %1;" : "=r"(r) : "f"(f));
    return r;
}
static __device__ __forceinline__ float roundtf(float f) {
    return __uint_as_float(f2tf32(f));
}
#define CPA16(dst, src) \
    asm volatile("cp.async.cg.shared.global [%0], [%1], 16;" :: "r"(dst), "l"(src))
#define CPA_COMMIT() asm volatile("cp.async.commit_group;" ::: "memory")
#define CPA_WAIT(n)  asm volatile("cp.async.wait_group %0;" :: "n"(n) : "memory")

static __device__ __forceinline__ void mma_tf32(float* c, const uint32_t* a,
                                                const uint32_t* b) {
    asm volatile(
        "mma.sync.aligned.m16n8k8.row.col.f32.tf32.tf32.f32 "
        "{%0,%1,%2,%3}, {%4,%5,%6,%7}, {%8,%9}, {%0,%1,%2,%3};"
        : "+f"(c[0]), "+f"(c[1]), "+f"(c[2]), "+f"(c[3])
        : "r"(a[0]), "r"(a[1]), "r"(a[2]), "r"(a[3]), "r"(b[0]), "r"(b[1]));
}

// byte offset of column cc within a permuted bf16 row (lane chunk layout)
static __device__ __forceinline__ int bfoff(int cc) {
    int c = cc & 127;
    int hi = (cc >> 7) & 1;
    return (c >> 2) * 16 + hi * 8 + (c & 3) * 2;
}

// ======================= round 3 weight matrices to tf32 (one launch) =======================
__global__ void round_w3(const float* __restrict__ w0, const float* __restrict__ w1,
                         const float* __restrict__ w2, float* __restrict__ out) {
    int b = blockIdx.x;
    int i = (b & 255) * 256 + threadIdx.x;
    const float* src = (b < 256) ? w0 : (b < 512) ? w1 : w2;
    out[(size_t)(b >> 8) * D_ * D_ + i] = roundtf(src[i]);
}

// ======================= zero bucket counters =======================
__global__ void zero_cnt(int* __restrict__ cnt) {
    int i = blockIdx.x * 256 + threadIdx.x;
    if (i < N_SP) cnt[i] = 0;
}

// ======================= tf32 mma.sync GEMM (cvt-free, 3-stage) =======================
#define BM 128
#define BN 128
#define BK 32
#define GK 256
#define NKT (GK / BK)
#define AS_STRIDE 36
#define BS_STRIDE 136
#define A_WORDS (BM * AS_STRIDE)
#define B_WORDS (BK * BS_STRIDE)
#define STAGE_WORDS (A_WORDS + B_WORDS)
#define GEMM_SMEM (3 * STAGE_WORDS * 4)   // 107520 B

__global__ void __launch_bounds__(256, 2)
mma_gemm(const float* __restrict__ A, const float* __restrict__ W,
         const float* __restrict__ bias, const float* __restrict__ skip,
         float* __restrict__ C, uint16_t* __restrict__ Cb, int Mtot)
{
    extern __shared__ float sm[];
    const int tid = threadIdx.x;
    const int wid = tid >> 5, lane = tid & 31;
    const int g = lane >> 2, t = lane & 3;
    const int wm = (wid >> 2) * 64;
    const int wn = (wid & 3) * 32;
    const int row0 = blockIdx.y * BM;
    const int col0 = blockIdx.x * BN;

    float c[4][4][4];
    #pragma unroll
    for (int i = 0; i < 4; i++)
        #pragma unroll
        for (int j = 0; j < 4; j++)
            { c[i][j][0] = 0.f; c[i][j][1] = 0.f; c[i][j][2] = 0.f; c[i][j][3] = 0.f; }

    uint32_t sbase = smem_u32(sm);

    auto issue_stage = [&](int kt, int buf) {
        uint32_t abase = sbase + buf * STAGE_WORDS * 4;
        uint32_t bbase = abase + A_WORDS * 4;
        int k0 = kt * BK;
        #pragma unroll
        for (int i = 0; i < 4; i++) {
            int idx = i * 256 + tid;
            int r = idx >> 3, cq = idx & 7;
            CPA16(abase + (r * AS_STRIDE + cq * 4) * 4,
                  A + (size_t)(row0 + r) * GK + k0 + cq * 4);
        }
        #pragma unroll
        for (int i = 0; i < 4; i++) {
            int idx = i * 256 + tid;
            int r = idx >> 5, cq = idx & 31;
            CPA16(bbase + (r * BS_STRIDE + cq * 4) * 4,
                  W + (size_t)(k0 + r) * GK + col0 + cq * 4);
        }
        CPA_COMMIT();
    };

    issue_stage(0, 0);
    issue_stage(1, 1);

    for (int kt = 0; kt < NKT; ++kt) {
        int buf = kt % 3;
        if (kt + 2 < NKT) { issue_stage(kt + 2, (kt + 2) % 3); CPA_WAIT(2); }
        else if (kt + 1 < NKT) { CPA_WAIT(1); }
        else { CPA_WAIT(0); }
        __syncthreads();

        const float* As = sm + buf * STAGE_WORDS;
        const float* Bs = As + A_WORDS;

        #pragma unroll
        for (int k8 = 0; k8 < BK / 8; k8++) {
            int kk = k8 * 8;
            uint32_t af[4][4], bf[4][2];
            #pragma unroll
            for (int mt = 0; mt < 4; mt++) {
                int m = wm + mt * 16;
                af[mt][0] = __float_as_uint(As[(m + g) * AS_STRIDE + kk + t]);
                af[mt][1] = __float_as_uint(As[(m + g + 8) * AS_STRIDE + kk + t]);
                af[mt][2] = __float_as_uint(As[(m + g) * AS_STRIDE + kk + t + 4]);
                af[mt][3] = __float_as_uint(As[(m + g + 8) * AS_STRIDE + kk + t + 4]);
            }
            #pragma unroll
            for (int nt = 0; nt < 4; nt++) {
                int n = wn + nt * 8;
                bf[nt][0] = __float_as_uint(Bs[(kk + t) * BS_STRIDE + n + g]);
                bf[nt][1] = __float_as_uint(Bs[(kk + t + 4) * BS_STRIDE + n + g]);
            }
            #pragma unroll
            for (int mt = 0; mt < 4; mt++)
                #pragma unroll
                for (int nt = 0; nt < 4; nt++)
                    mma_tf32(c[mt][nt], af[mt], bf[nt]);
        }
        __syncthreads();
    }

    if (Cb) {
        #pragma unroll
        for (int mt = 0; mt < 4; mt++) {
            int r0 = row0 + wm + mt * 16 + g;
            int r1 = r0 + 8;
            char* rp0 = (char*)(Cb + (size_t)r0 * D_);
            char* rp1 = (char*)(Cb + (size_t)r1 * D_);
            #pragma unroll
            for (int nt = 0; nt < 4; nt++) {
                int cc = col0 + wn + nt * 8 + 2 * t;
                float b0 = bias[cc], b1 = bias[cc + 1];
                int off = bfoff(cc);
                __nv_bfloat162 h0 = __floats2bfloat162_rn(c[mt][nt][0] + b0,
                                                          c[mt][nt][1] + b1);
                __nv_bfloat162 h1 = __floats2bfloat162_rn(c[mt][nt][2] + b0,
                                                          c[mt][nt][3] + b1);
                *(__nv_bfloat162*)(rp0 + off) = h0;
                *(__nv_bfloat162*)(rp1 + off) = h1;
            }
        }
    } else {
        #pragma unroll
        for (int mt = 0; mt < 4; mt++) {
            int r0 = row0 + wm + mt * 16 + g;
            int r1 = r0 + 8;
            #pragma unroll
            for (int nt = 0; nt < 4; nt++) {
                int cc = col0 + wn + nt * 8 + 2 * t;
                float b0 = bias[cc], b1 = bias[cc + 1];
                if (r0 < Mtot) {
                    float2 v = { c[mt][nt][0] + b0, c[mt][nt][1] + b1 };
                    if (skip) {
                        const float2 s2 = *(const float2*)(skip + (size_t)r0 * D_ + cc);
                        v.x += s2.x; v.y += s2.y;
                    }
                    *(float2*)(C + (size_t)r0 * D_ + cc) = v;
                }
                if (r1 < Mtot) {
                    float2 v = { c[mt][nt][2] + b0, c[mt][nt][3] + b1 };
                    if (skip) {
                        const float2 s2 = *(const float2*)(skip + (size_t)r1 * D_ + cc);
                        v.x += s2.x; v.y += s2.y;
                    }
                    *(float2*)(C + (size_t)r1 * D_ + cc) = v;
                }
            }
        }
    }
}

// ======================= warp reduce helper =======================
static __device__ __forceinline__ void wreduce2(float& s, float& q) {
    #pragma unroll
    for (int o = 16; o; o >>= 1) {
        s += __shfl_xor_sync(0xffffffffu, s, o);
        q += __shfl_xor_sync(0xffffffffu, q, o);
    }
}
#define SUM4(v) ((v).x + (v).y + (v).z + (v).w)
#define SUMSQ4(v) ((v).x*(v).x + (v).y*(v).y + (v).z*(v).z + (v).w*(v).w)

// ======================= LN1 + ReLU (tf32 out) — warp/row =======================
__global__ void __launch_bounds__(256)
ln_relu_kernel(const float* __restrict__ x,
               const float* __restrict__ g,
               const float* __restrict__ b,
               float* __restrict__ out) {
    int row = blockIdx.x * 8 + (threadIdx.x >> 5);
    int lane = threadIdx.x & 31;

    const float4* xp = (const float4*)(x + (size_t)row * D_);
    float4 v0 = xp[lane], v1 = xp[lane + 32];
    float s = SUM4(v0) + SUM4(v1);
    float q = SUMSQ4(v0) + SUMSQ4(v1);
    wreduce2(s, q);
    float mean = s * (1.f / 256.f);
    float var  = q * (1.f / 256.f) - mean * mean;
    float rstd = rsqrtf(var + 1e-5f);

    float4 g0 = ((const float4*)g)[lane], g1 = ((const float4*)g)[lane + 32];
    float4 b0 = ((const float4*)b)[lane], b1 = ((const float4*)b)[lane + 32];
    float4 y0, y1;
    y0.x = roundtf(fmaxf((v0.x - mean) * rstd * g0.x + b0.x, 0.f));
    y0.y = roundtf(fmaxf((v0.y - mean) * rstd * g0.y + b0.y, 0.f));
    y0.z = roundtf(fmaxf((v0.z - mean) * rstd * g0.z + b0.z, 0.f));
    y0.w = roundtf(fmaxf((v0.w - mean) * rstd * g0.w + b0.w, 0.f));
    y1.x = roundtf(fmaxf((v1.x - mean) * rstd * g1.x + b1.x, 0.f));
    y1.y = roundtf(fmaxf((v1.y - mean) * rstd * g1.y + b1.y, 0.f));
    y1.z = roundtf(fmaxf((v1.z - mean) * rstd * g1.z + b1.z, 0.f));
    y1.w = roundtf(fmaxf((v1.w - mean) * rstd * g1.w + b1.w, 0.f));
    float4* op = (float4*)(out + (size_t)row * D_);
    op[lane] = y0; op[lane + 32] = y1;
}

// ======================= bucket fill: edges -> per-target slots =======================
__global__ void bucket_fill(const int* __restrict__ etgt,
                            int* __restrict__ cnt, int* __restrict__ bucket) {
    int e = blockIdx.x * 256 + threadIdx.x;
    if (e >= N_PROJ) return;
    int tgt = etgt[e];
    int slot = atomicAdd(cnt + tgt, 1);
    if (slot < BUCKET_CAP) bucket[(size_t)tgt * BUCKET_CAP + slot] = e;
}

// ======================= aggregate + finalize (one warp per target) =======================
__global__ void __launch_bounds__(256)
agg_finalize(const int* __restrict__ cnt, const int* __restrict__ bucket,
             const int* __restrict__ esrc, const float* __restrict__ att,
             const uint16_t* __restrict__ xlb, const float* __restrict__ xr,
             const float* __restrict__ prev, const float* __restrict__ gat_bias,
             const float* __restrict__ g2, const float* __restrict__ b2,
             float* __restrict__ xskip, float* __restrict__ hbuf)
{
    int tgt = blockIdx.x * 8 + (threadIdx.x >> 5);
    int lane = threadIdx.x & 31;
    int n = min(cnt[tgt], BUCKET_CAP);

    const float4* xrp = (const float4*)(xr + (size_t)tgt * 256);
    float4 r0 = xrp[lane], r1 = xrp[lane + 32];
    int h1 = lane >> 3;
    const float4 w0 = *(const float4*)(att + h1 * 32 + ((lane & 7) << 2));
    const float4 w1 = *(const float4*)(att + (h1 + 4) * 32 + ((lane & 7) << 2));

    const int* bp = bucket + (size_t)tgt * BUCKET_CAP;
    int sA = 0, sB = 0;
    if (lane < n)      sA = esrc[bp[lane]];
    if (lane + 32 < n) sB = esrc[bp[lane + 32]];

    auto loadrow = [&](int i) {
        int s = (i < 32) ? __shfl_sync(0xffffffffu, sA, i)
                         : __shfl_sync(0xffffffffu, sB, i - 32);
        return ((const uint4*)(xlb + (size_t)s * 256))[lane];
    };

    float4 acc0 = {0.f,0.f,0.f,0.f}, acc1 = {0.f,0.f,0.f,0.f};
    float den1 = 0.f, den2 = 0.f;

    uint4 q0 = {}, q1 = {};
    if (n > 0) q0 = loadrow(0);
    if (n > 1) q1 = loadrow(1);

    for (int i = 0; i < n; i++) {
        uint4 qn = {};
        if (i + 2 < n) qn = loadrow(i + 2);

        float2 f0 = __bfloat1622float2(*(const __nv_bfloat162*)&q0.x);
        float2 f1 = __bfloat1622float2(*(const __nv_bfloat162*)&q0.y);
        float2 f2 = __bfloat1622float2(*(const __nv_bfloat162*)&q0.z);
        float2 f3 = __bfloat1622float2(*(const __nv_bfloat162*)&q0.w);
        float4 a0 = { f0.x, f0.y, f1.x, f1.y };
        float4 a1 = { f2.x, f2.y, f3.x, f3.y };

        #define LREL(x) (fmaxf((x), 0.f) + 0.2f * fminf((x), 0.f))
        float p1 = LREL(a0.x + r0.x) * w0.x + LREL(a0.y + r0.y) * w0.y +
                   LREL(a0.z + r0.z) * w0.z + LREL(a0.w + r0.w) * w0.w;
        float p2 = LREL(a1.x + r1.x) * w1.x + LREL(a1.y + r1.y) * w1.y +
                   LREL(a1.z + r1.z) * w1.z + LREL(a1.w + r1.w) * w1.w;
        #undef LREL
        #pragma unroll
        for (int o = 4; o; o >>= 1) {
            p1 += __shfl_xor_sync(0xffffffffu, p1, o);
            p2 += __shfl_xor_sync(0xffffffffu, p2, o);
        }
        float ex1 = expf(p1);
        float ex2 = expf(p2);
        acc0.x += ex1 * a0.x; acc0.y += ex1 * a0.y;
        acc0.z += ex1 * a0.z; acc0.w += ex1 * a0.w;
        acc1.x += ex2 * a1.x; acc1.y += ex2 * a1.y;
        acc1.z += ex2 * a1.z; acc1.w += ex2 * a1.w;
        den1 += ex1; den2 += ex2;

        q0 = q1; q1 = qn;
    }

    float inv1 = 1.f / (den1 + 1e-16f);
    float inv2 = 1.f / (den2 + 1e-16f);
    const float4* pp = (const float4*)(prev + (size_t)tgt * D_);
    float4 p0 = pp[lane], p1v = pp[lane + 32];
    float4 gb0 = ((const float4*)gat_bias)[lane];
    float4 gb1 = ((const float4*)gat_bias)[lane + 32];

    float4 x0, x1;
    x0.x = p0.x + acc0.x * inv1 + gb0.x;
    x0.y = p0.y + acc0.y * inv1 + gb0.y;
    x0.z = p0.z + acc0.z * inv1 + gb0.z;
    x0.w = p0.w + acc0.w * inv1 + gb0.w;
    x1.x = p1v.x + acc1.x * inv2 + gb1.x;
    x1.y = p1v.y + acc1.y * inv2 + gb1.y;
    x1.z = p1v.z + acc1.z * inv2 + gb1.z;
    x1.w = p1v.w + acc1.w * inv2 + gb1.w;

    float4* sk = (float4*)(xskip + (size_t)tgt * D_);
    sk[lane] = x0; sk[lane + 32] = x1;

    float s = SUM4(x0) + SUM4(x1);
    float q = SUMSQ4(x0) + SUMSQ4(x1);
    wreduce2(s, q);
    float mean = s * (1.f / 256.f);
    float var  = q * (1.f / 256.f) - mean * mean;
    float rstd = rsqrtf(var + 1e-5f);

    float4 g0 = ((const float4*)g2)[lane], g1 = ((const float4*)g2)[lane + 32];
    float4 bb0 = ((const float4*)b2)[lane], bb1 = ((const float4*)b2)[lane + 32];
    float4 y0, y1;
    y0.x = roundtf(fmaxf((x0.x - mean) * rstd * g0.x + bb0.x, 0.f));
    y0.y = roundtf(fmaxf((x0.y - mean) * rstd * g0.y + bb0.y, 0.f));
    y0.z = roundtf(fmaxf((x0.z - mean) * rstd * g0.z + bb0.z, 0.f));
    y0.w = roundtf(fmaxf((x0.w - mean) * rstd * g0.w + bb0.w, 0.f));
    y1.x = roundtf(fmaxf((x1.x - mean) * rstd * g1.x + bb1.x, 0.f));
    y1.y = roundtf(fmaxf((x1.y - mean) * rstd * g1.y + bb1.y, 0.f));
    y1.z = roundtf(fmaxf((x1.z - mean) * rstd * g1.z + bb1.z, 0.f));
    y1.w = roundtf(fmaxf((x1.w - mean) * rstd * g1.w + bb1.w, 0.f));
    float4* hp = (float4*)(hbuf + (size_t)tgt * D_);
    hp[lane] = y0; hp[lane + 32] = y1;
}

// ======================= launch =======================
extern "C" void kernel_launch(void* const* d_in, const int* in_sizes, int n_in,
                              void* d_out, int out_size) {
    const float* proj     = (const float*)d_in[0];
    const float* prev     = (const float*)d_in[1];
    const float* Wl       = (const float*)d_in[2];
    const float* bl       = (const float*)d_in[3];
    const float* Wr       = (const float*)d_in[4];
    const float* br       = (const float*)d_in[5];
    const float* att      = (const float*)d_in[6];
    const float* gat_bias = (const float*)d_in[7];
    const float* ln1_g    = (const float*)d_in[8];
    const float* ln1_b    = (const float*)d_in[9];
    const float* ln2_g    = (const float*)d_in[10];
    const float* ln2_b    = (const float*)d_in[11];
    const float* mlp_W    = (const float*)d_in[12];
    const float* mlp_b    = (const float*)d_in[13];
    const int*   esrc     = (const int*)d_in[14];
    const int*   etgt     = (const int*)d_in[15];
    float* out = (float*)d_out;

    float *p_xagg, *p_xr, *p_xskip, *p_hbuf, *p_wr;
    uint16_t* p_xlb;
    int *p_cnt, *p_bucket;
    cudaGetSymbolAddress((void**)&p_xlb, g_xlb);
    cudaGetSymbolAddress((void**)&p_xagg, g_xagg);
    cudaGetSymbolAddress((void**)&p_xr, g_xr);
    cudaGetSymbolAddress((void**)&p_xskip, g_xskip);
    cudaGetSymbolAddress((void**)&p_hbuf, g_hbuf);
    cudaGetSymbolAddress((void**)&p_wr, g_wr);
    cudaGetSymbolAddress((void**)&p_cnt, g_cnt);
    cudaGetSymbolAddress((void**)&p_bucket, g_bucket);
    float* wlR  = p_wr;
    float* wrR  = p_wr + (size_t)D_ * D_;
    float* mlpR = p_wr + 2 * (size_t)D_ * D_;

    cudaFuncSetAttribute(mma_gemm, cudaFuncAttributeMaxDynamicSharedMemorySize, GEMM_SMEM);

    // side stream + fork/join events (host-side objects; created per call,
    // destroyed after join — replay cost unaffected, capture records the DAG)
    cudaStream_t s2;
    cudaEvent_t e0, e2;
    cudaStreamCreateWithFlags(&s2, cudaStreamNonBlocking);
    cudaEventCreateWithFlags(&e0, cudaEventDisableTiming);
    cudaEventCreateWithFlags(&e2, cudaEventDisableTiming);

    // s0: weight rounding first (xr GEMM on s2 needs wrR)
    round_w3<<<768, 256>>>(Wl, Wr, mlp_W, p_wr);
    cudaEventRecord(e0, 0);

    // ---- fork: s2 runs ln_relu -> xr GEMM concurrently with s0's xl chain ----
    cudaStreamWaitEvent(s2, e0, 0);
    ln_relu_kernel<<<N_SP / 8, 256, 0, s2>>>(prev, ln1_g, ln1_b, p_xagg);
    {
        dim3 grid(D_ / BN, SP_PAD / BM);
        mma_gemm<<<grid, 256, GEMM_SMEM, s2>>>(p_xagg, wrR, br, nullptr,
                                               p_xr, nullptr, N_SP);
    }
    cudaEventRecord(e2, s2);

    // ---- s0: bucket + xl GEMM ----
    zero_cnt<<<(N_SP + 255) / 256, 256>>>(p_cnt);
    bucket_fill<<<(N_PROJ + 255) / 256, 256>>>(etgt, p_cnt, p_bucket);
    {
        dim3 grid(D_ / BN, N_PROJ / BM);
        mma_gemm<<<grid, 256, GEMM_SMEM>>>(proj, wlR, bl, nullptr,
                                           nullptr, p_xlb, N_PROJ);
    }

    // ---- join ----
    cudaStreamWaitEvent(0, e2, 0);

    // aggregate per-target + finalize (residual + LN2 + relu), fused
    agg_finalize<<<N_SP / 8, 256>>>(p_cnt, p_bucket, esrc, att, p_xlb, p_xr,
                                    prev, gat_bias, ln2_g, ln2_b, p_xskip, p_hbuf);

    // out = xskip + hbuf @ mlp_W + mlp_b
    {
        dim3 grid(D_ / BN, SP_PAD / BM);
        mma_gemm<<<grid, 256, GEMM_SMEM>>>(p_hbuf, mlpR, mlp_b, p_xskip,
                                           out, nullptr, N_SP);
    }

    cudaEventDestroy(e0);
    cudaEventDestroy(e2);
    cudaStreamDestroy(s2);
}